// round 1
// baseline (speedup 1.0000x reference)
#include <cuda_runtime.h>
#include <math.h>

#define T_SEQ 2048
#define BATCH 2
#define DMODEL 2048
#define HQ 16
#define HKV 4
#define HD 128
#define M_ROWS (BATCH*T_SEQ)   /* 4096 */
#define DKV (HKV*HD)           /* 512 */

// ---------------- scratch (device globals: no allocation allowed) ----------
__device__ float g_Q[M_ROWS*DMODEL];
__device__ float g_K[M_ROWS*DKV];
__device__ float g_V[M_ROWS*DKV];
__device__ float g_AO[M_ROWS*DMODEL];
__device__ float g_cos[T_SEQ*64];
__device__ float g_sin[T_SEQ*64];

// ---------------- RoPE table (fp64 trig for accuracy at large angles) ------
__global__ void rope_table_kernel() {
    int idx = blockIdx.x*blockDim.x + threadIdx.x;
    if (idx >= T_SEQ*64) return;
    int t = idx >> 6, i = idx & 63;
    float inv = powf(10000.0f, -(float)i / 64.0f);
    float ang = (float)t * inv;
    g_cos[idx] = (float)cos((double)ang);
    g_sin[idx] = (float)sin((double)ang);
}

// buf layout: [M_ROWS][heads*128]; rotates pairs (i, i+64) within each head
__global__ void rope_apply_kernel(float* __restrict__ buf, int heads) {
    int idx = blockIdx.x*blockDim.x + threadIdx.x;
    int total = M_ROWS * heads * 64;
    if (idx >= total) return;
    int i = idx & 63;
    int h = (idx >> 6) % heads;
    int m = idx / (64 * heads);
    int t = m & (T_SEQ - 1);
    float c = g_cos[t*64 + i], s = g_sin[t*64 + i];
    float* p = buf + (size_t)m * heads * HD + h * HD + i;
    float a = p[0], b = p[64];
    p[0]  = a*c - b*s;
    p[64] = b*c + a*s;
}

// ---------------- 128x128x8 SGEMM, 8x8 register blocking, 256 threads ------
// C[M,N] = A[M,K] @ B[K,N], all row-major, M%128==0, N%128==0, K%8==0
__global__ __launch_bounds__(256) void sgemm128(
    const float* __restrict__ A, const float* __restrict__ B,
    float* __restrict__ C, int M, int N, int K)
{
    __shared__ float As[8][128];   // transposed A tile
    __shared__ float Bs[8][128];

    const int tid = threadIdx.x;
    const int bm = blockIdx.y * 128;
    const int bn = blockIdx.x * 128;

    const int arow = tid >> 1;          // 0..127
    const int acol = (tid & 1) * 4;     // 0 or 4
    const int brow = tid >> 5;          // 0..7
    const int bcol = (tid & 31) * 4;    // 0..124
    const int ty = tid >> 4;            // 0..15
    const int tx = tid & 15;            // 0..15

    float acc[8][8];
    #pragma unroll
    for (int i = 0; i < 8; i++)
        #pragma unroll
        for (int j = 0; j < 8; j++) acc[i][j] = 0.f;

    const float* Aptr = A + (size_t)(bm + arow) * K + acol;
    const float* Bptr = B + (size_t)brow * N + bn + bcol;

    for (int k0 = 0; k0 < K; k0 += 8) {
        float4 a4 = *(const float4*)Aptr;  Aptr += 8;
        float4 b4 = *(const float4*)Bptr;  Bptr += (size_t)8 * N;
        As[acol+0][arow] = a4.x;
        As[acol+1][arow] = a4.y;
        As[acol+2][arow] = a4.z;
        As[acol+3][arow] = a4.w;
        *(float4*)(&Bs[brow][bcol]) = b4;
        __syncthreads();

        #pragma unroll
        for (int k = 0; k < 8; ++k) {
            float ar[8], br[8];
            #pragma unroll
            for (int i = 0; i < 8; i++) ar[i] = As[k][ty*8 + i];
            #pragma unroll
            for (int j = 0; j < 8; j++) br[j] = Bs[k][tx*8 + j];
            #pragma unroll
            for (int i = 0; i < 8; i++)
                #pragma unroll
                for (int j = 0; j < 8; j++)
                    acc[i][j] += ar[i] * br[j];
        }
        __syncthreads();
    }

    #pragma unroll
    for (int i = 0; i < 8; i++) {
        float* crow = C + (size_t)(bm + ty*8 + i) * N + bn + tx*8;
        *(float4*)(crow)     = make_float4(acc[i][0], acc[i][1], acc[i][2], acc[i][3]);
        *(float4*)(crow + 4) = make_float4(acc[i][4], acc[i][5], acc[i][6], acc[i][7]);
    }
}

// ---------------- Flash attention (causal, GQA), fp32, BQ=BK=64 ------------
#define FA_NEG (-3.0e38f)
#define FA_SCALE 0.08838834764831845f   /* 128^-0.5 */
#define QS_LD 132
#define SS_LD 68
#define FA_SMEM_FLOATS (3*64*QS_LD + 64*SS_LD + 3*64)
#define FA_SMEM_BYTES (FA_SMEM_FLOATS*4)

__global__ __launch_bounds__(256) void flash_kernel(
    const float* __restrict__ Q, const float* __restrict__ K,
    const float* __restrict__ V, float* __restrict__ AO)
{
    const int qt = blockIdx.x;       // 0..31 (q tile of 64)
    const int h  = blockIdx.y;       // 0..15
    const int b  = blockIdx.z;       // 0..1
    const int hk = h >> 2;           // GQA: repeat_interleave -> h//4
    const int tid = threadIdx.x;

    extern __shared__ float sm[];
    float* Qs = sm;                      // 64 x 132
    float* Ks = Qs + 64*QS_LD;           // 64 x 132
    float* Vs = Ks + 64*QS_LD;           // 64 x 132
    float* Ss = Vs + 64*QS_LD;           // 64 x 68
    float* rm = Ss + 64*SS_LD;           // 64 running max
    float* rl = rm + 64;                 // 64 running sum
    float* rc = rl + 64;                 // 64 correction

    const int base_q = b*T_SEQ + qt*64;

    // load Q tile (row r, 32 float4 per row)
    for (int x = tid; x < 64*32; x += 256) {
        int r = x >> 5, c4 = (x & 31) * 4;
        *(float4*)(Qs + r*QS_LD + c4) =
            *(const float4*)(Q + (size_t)(base_q + r)*DMODEL + h*HD + c4);
    }
    if (tid < 64) { rm[tid] = FA_NEG; rl[tid] = 0.f; }

    float acc[4][8];
    #pragma unroll
    for (int i = 0; i < 4; i++)
        #pragma unroll
        for (int j = 0; j < 8; j++) acc[i][j] = 0.f;

    const int r0  = (tid >> 4) * 4;   // S/O row base (0..60)
    const int c0  = (tid & 15) * 4;   // S col base (0..60)
    const int oc0 = (tid & 15) * 8;   // O col base (0..120)

    __syncthreads();

    for (int kt = 0; kt <= qt; ++kt) {
        const int base_k = b*T_SEQ + kt*64;
        // load K and V tiles
        for (int x = tid; x < 64*32; x += 256) {
            int r = x >> 5, c4 = (x & 31) * 4;
            *(float4*)(Ks + r*QS_LD + c4) =
                *(const float4*)(K + (size_t)(base_k + r)*DKV + hk*HD + c4);
            *(float4*)(Vs + r*QS_LD + c4) =
                *(const float4*)(V + (size_t)(base_k + r)*DKV + hk*HD + c4);
        }
        __syncthreads();

        // S = Q K^T (4x4 per thread over 64x64)
        float sreg[4][4];
        #pragma unroll
        for (int i = 0; i < 4; i++)
            #pragma unroll
            for (int j = 0; j < 4; j++) sreg[i][j] = 0.f;

        #pragma unroll 4
        for (int d = 0; d < 128; d += 4) {
            float4 q4[4], k4[4];
            #pragma unroll
            for (int i = 0; i < 4; i++) q4[i] = *(const float4*)(Qs + (r0+i)*QS_LD + d);
            #pragma unroll
            for (int j = 0; j < 4; j++) k4[j] = *(const float4*)(Ks + (c0+j)*QS_LD + d);
            #pragma unroll
            for (int i = 0; i < 4; i++)
                #pragma unroll
                for (int j = 0; j < 4; j++) {
                    sreg[i][j] += q4[i].x*k4[j].x;
                    sreg[i][j] += q4[i].y*k4[j].y;
                    sreg[i][j] += q4[i].z*k4[j].z;
                    sreg[i][j] += q4[i].w*k4[j].w;
                }
        }
        const bool diag = (kt == qt);
        #pragma unroll
        for (int i = 0; i < 4; i++)
            #pragma unroll
            for (int j = 0; j < 4; j++) {
                float v = sreg[i][j] * FA_SCALE;
                if (diag && (c0 + j) > (r0 + i)) v = FA_NEG;
                Ss[(r0+i)*SS_LD + c0 + j] = v;
            }
        __syncthreads();

        // online softmax: one thread per row
        if (tid < 64) {
            const int r = tid;
            float mold = rm[r];
            float mx = mold;
            #pragma unroll 8
            for (int j = 0; j < 64; ++j) mx = fmaxf(mx, Ss[r*SS_LD + j]);
            float corr = __expf(mold - mx);
            float sum = 0.f;
            #pragma unroll 8
            for (int j = 0; j < 64; ++j) {
                float p = __expf(Ss[r*SS_LD + j] - mx);
                Ss[r*SS_LD + j] = p;
                sum += p;
            }
            rm[r] = mx;
            rl[r] = rl[r]*corr + sum;
            rc[r] = corr;
        }
        __syncthreads();

        // O = O*corr + P @ V   (4 rows x 8 cols per thread)
        {
            float cr[4];
            #pragma unroll
            for (int i = 0; i < 4; i++) cr[i] = rc[r0 + i];
            #pragma unroll
            for (int i = 0; i < 4; i++)
                #pragma unroll
                for (int j = 0; j < 8; j++) acc[i][j] *= cr[i];

            #pragma unroll 4
            for (int jj = 0; jj < 64; ++jj) {
                float p0 = Ss[(r0+0)*SS_LD + jj];
                float p1 = Ss[(r0+1)*SS_LD + jj];
                float p2 = Ss[(r0+2)*SS_LD + jj];
                float p3 = Ss[(r0+3)*SS_LD + jj];
                float4 va = *(const float4*)(Vs + jj*QS_LD + oc0);
                float4 vb = *(const float4*)(Vs + jj*QS_LD + oc0 + 4);
                acc[0][0] += p0*va.x; acc[0][1] += p0*va.y; acc[0][2] += p0*va.z; acc[0][3] += p0*va.w;
                acc[0][4] += p0*vb.x; acc[0][5] += p0*vb.y; acc[0][6] += p0*vb.z; acc[0][7] += p0*vb.w;
                acc[1][0] += p1*va.x; acc[1][1] += p1*va.y; acc[1][2] += p1*va.z; acc[1][3] += p1*va.w;
                acc[1][4] += p1*vb.x; acc[1][5] += p1*vb.y; acc[1][6] += p1*vb.z; acc[1][7] += p1*vb.w;
                acc[2][0] += p2*va.x; acc[2][1] += p2*va.y; acc[2][2] += p2*va.z; acc[2][3] += p2*va.w;
                acc[2][4] += p2*vb.x; acc[2][5] += p2*vb.y; acc[2][6] += p2*vb.z; acc[2][7] += p2*vb.w;
                acc[3][0] += p3*va.x; acc[3][1] += p3*va.y; acc[3][2] += p3*va.z; acc[3][3] += p3*va.w;
                acc[3][4] += p3*vb.x; acc[3][5] += p3*vb.y; acc[3][6] += p3*vb.z; acc[3][7] += p3*vb.w;
            }
        }
        __syncthreads();
    }

    // epilogue: divide by running sum, write AO
    #pragma unroll
    for (int i = 0; i < 4; i++) {
        float inv = 1.0f / rl[r0 + i];
        float* dst = AO + (size_t)(base_q + r0 + i)*DMODEL + h*HD + oc0;
        *(float4*)(dst)     = make_float4(acc[i][0]*inv, acc[i][1]*inv, acc[i][2]*inv, acc[i][3]*inv);
        *(float4*)(dst + 4) = make_float4(acc[i][4]*inv, acc[i][5]*inv, acc[i][6]*inv, acc[i][7]*inv);
    }
}

// ---------------- launch --------------------------------------------------
extern "C" void kernel_launch(void* const* d_in, const int* in_sizes, int n_in,
                              void* d_out, int out_size)
{
    const float* x  = (const float*)d_in[0];
    const float* Wq = (const float*)d_in[1];
    const float* Wk = (const float*)d_in[2];
    const float* Wv = (const float*)d_in[3];
    const float* Wo = (const float*)d_in[4];
    float* out = (float*)d_out;

    float *Q, *K, *V, *AO;
    cudaGetSymbolAddress((void**)&Q,  g_Q);
    cudaGetSymbolAddress((void**)&K,  g_K);
    cudaGetSymbolAddress((void**)&V,  g_V);
    cudaGetSymbolAddress((void**)&AO, g_AO);

    cudaFuncSetAttribute(flash_kernel,
                         cudaFuncAttributeMaxDynamicSharedMemorySize, FA_SMEM_BYTES);

    // RoPE cos/sin table
    rope_table_kernel<<<(T_SEQ*64 + 255)/256, 256>>>();

    // projections
    sgemm128<<<dim3(DMODEL/128, M_ROWS/128), 256>>>(x, Wq, Q, M_ROWS, DMODEL, DMODEL);
    sgemm128<<<dim3(DKV/128,    M_ROWS/128), 256>>>(x, Wk, K, M_ROWS, DKV,    DMODEL);
    sgemm128<<<dim3(DKV/128,    M_ROWS/128), 256>>>(x, Wv, V, M_ROWS, DKV,    DMODEL);

    // RoPE on Q and K
    rope_apply_kernel<<<(M_ROWS*HQ*64  + 255)/256, 256>>>(Q, HQ);
    rope_apply_kernel<<<(M_ROWS*HKV*64 + 255)/256, 256>>>(K, HKV);

    // causal GQA flash attention
    flash_kernel<<<dim3(T_SEQ/64, HQ, BATCH), 256, FA_SMEM_BYTES>>>(Q, K, V, AO);

    // output projection
    sgemm128<<<dim3(DMODEL/128, M_ROWS/128), 256>>>(AO, Wo, out, M_ROWS, DMODEL, DMODEL);
}

// round 3
// speedup vs baseline: 3.5741x; 3.5741x over previous
#include <cuda_runtime.h>
#include <math.h>
#include <stdint.h>

#define T_SEQ 2048
#define BATCH 2
#define DMODEL 2048
#define HQ 16
#define HKV 4
#define HD 128
#define M_ROWS (BATCH*T_SEQ)   /* 4096 */
#define DKV (HKV*HD)           /* 512 */
#define FA_SCALE 0.08838834764831845f

// ---------------- scratch ---------------------------------------------------
__device__ float g_Q[M_ROWS*DMODEL];
__device__ float g_K[M_ROWS*DKV];
__device__ float g_V[M_ROWS*DKV];
__device__ float g_AO[M_ROWS*DMODEL];
__device__ float g_cos[T_SEQ*64];
__device__ float g_sin[T_SEQ*64];

// ---------------- helpers ----------------------------------------------------
__device__ __forceinline__ uint32_t cvt_tf32(float f) {
    uint32_t r; asm("cvt.rna.tf32.f32 %0, %1;" : "=r"(r) : "f"(f)); return r;
}
// D(16x8) += A(16x8,row) * B(8x8,col) ; tf32 inputs, f32 accum
__device__ __forceinline__ void mma8(float* d, const uint32_t* a, const uint32_t* b) {
    asm volatile("mma.sync.aligned.m16n8k8.row.col.f32.tf32.tf32.f32 "
        "{%0,%1,%2,%3}, {%4,%5,%6,%7}, {%8,%9}, {%0,%1,%2,%3};"
        : "+f"(d[0]), "+f"(d[1]), "+f"(d[2]), "+f"(d[3])
        : "r"(a[0]), "r"(a[1]), "r"(a[2]), "r"(a[3]), "r"(b[0]), "r"(b[1]));
}

// ---------------- RoPE ------------------------------------------------------
__global__ void rope_table_kernel() {
    int idx = blockIdx.x*blockDim.x + threadIdx.x;
    if (idx >= T_SEQ*64) return;
    int t = idx >> 6, i = idx & 63;
    float inv = powf(10000.0f, -(float)i / 64.0f);
    float ang = (float)t * inv;
    g_cos[idx] = (float)cos((double)ang);
    g_sin[idx] = (float)sin((double)ang);
}

__global__ void rope_apply_kernel(float* __restrict__ buf, int heads) {
    int idx = blockIdx.x*blockDim.x + threadIdx.x;
    int total = M_ROWS * heads * 64;
    if (idx >= total) return;
    int i = idx & 63;
    int h = (idx >> 6) % heads;
    int m = idx / (64 * heads);
    int t = m & (T_SEQ - 1);
    float c = g_cos[t*64 + i], s = g_sin[t*64 + i];
    float* p = buf + (size_t)m * heads * HD + h * HD + i;
    float a = p[0], b = p[64];
    p[0]  = a*c - b*s;
    p[64] = b*c + a*s;
}

// ---------------- tf32 mma.sync GEMM: C[M,N] = A[M,K] @ B[K,N] ---------------
// 128x128 CTA tile, 8 warps (4x2), warp tile 32x64, K-chunk 32.
__global__ __launch_bounds__(256) void tc_gemm(
    const float* __restrict__ A, const float* __restrict__ B,
    float* __restrict__ C, int M, int N, int K)
{
    __shared__ uint32_t As[128][36];   // [m][k] pad->conflict-free frag reads
    __shared__ uint32_t Bs[32][136];   // [k][n]

    const int tid = threadIdx.x;
    const int wid = tid >> 5, lane = tid & 31;
    const int gid = lane >> 2, tig = lane & 3;
    const int wm = wid & 3, wn = wid >> 2;   // warp row/col block
    const int bm = blockIdx.y * 128;
    const int bn = blockIdx.x * 128;
    const int nc = K >> 5;

    float acc[2][8][4];
    #pragma unroll
    for (int mt = 0; mt < 2; mt++)
        #pragma unroll
        for (int nt = 0; nt < 8; nt++)
            #pragma unroll
            for (int e = 0; e < 4; e++) acc[mt][nt][e] = 0.f;

    // prefetch registers (chunk granularity): A 4 x float4, B 4 x float4
    float4 pa[4], pb[4];
    const int ar = tid >> 3, ac4 = tid & 7;      // A: rows ar+32i, col4 ac4
    const int bk = tid >> 5, bn4 = tid & 31;     // B: rows bk+8i, col4 bn4

    #pragma unroll
    for (int i = 0; i < 4; i++)
        pa[i] = *(const float4*)(A + (size_t)(bm + ar + 32*i) * K + ac4*4);
    #pragma unroll
    for (int i = 0; i < 4; i++)
        pb[i] = *(const float4*)(B + (size_t)(bk + 8*i) * N + bn + bn4*4);

    for (int c = 0; c < nc; ++c) {
        // store prefetched chunk with RNE tf32 conversion
        #pragma unroll
        for (int i = 0; i < 4; i++) {
            uint32_t* d = &As[ar + 32*i][ac4*4];
            d[0] = cvt_tf32(pa[i].x); d[1] = cvt_tf32(pa[i].y);
            d[2] = cvt_tf32(pa[i].z); d[3] = cvt_tf32(pa[i].w);
        }
        #pragma unroll
        for (int i = 0; i < 4; i++) {
            uint32_t* d = &Bs[bk + 8*i][bn4*4];
            d[0] = cvt_tf32(pb[i].x); d[1] = cvt_tf32(pb[i].y);
            d[2] = cvt_tf32(pb[i].z); d[3] = cvt_tf32(pb[i].w);
        }
        __syncthreads();

        // prefetch next chunk
        if (c + 1 < nc) {
            const int ko = (c + 1) << 5;
            #pragma unroll
            for (int i = 0; i < 4; i++)
                pa[i] = *(const float4*)(A + (size_t)(bm + ar + 32*i) * K + ko + ac4*4);
            #pragma unroll
            for (int i = 0; i < 4; i++)
                pb[i] = *(const float4*)(B + (size_t)(ko + bk + 8*i) * N + bn + bn4*4);
        }

        // compute: 4 k-steps of 8
        #pragma unroll
        for (int ks = 0; ks < 4; ++ks) {
            uint32_t af[2][4];
            #pragma unroll
            for (int mt = 0; mt < 2; mt++) {
                int r0 = wm*32 + mt*16 + gid;
                af[mt][0] = As[r0    ][ks*8 + tig];
                af[mt][1] = As[r0 + 8][ks*8 + tig];
                af[mt][2] = As[r0    ][ks*8 + tig + 4];
                af[mt][3] = As[r0 + 8][ks*8 + tig + 4];
            }
            uint32_t bf[8][2];
            #pragma unroll
            for (int nt = 0; nt < 8; nt++) {
                int col = wn*64 + nt*8 + gid;
                bf[nt][0] = Bs[ks*8 + tig    ][col];
                bf[nt][1] = Bs[ks*8 + tig + 4][col];
            }
            #pragma unroll
            for (int mt = 0; mt < 2; mt++)
                #pragma unroll
                for (int nt = 0; nt < 8; nt++)
                    mma8(acc[mt][nt], af[mt], bf[nt]);
        }
        __syncthreads();
    }

    // epilogue
    #pragma unroll
    for (int mt = 0; mt < 2; mt++) {
        int r0 = bm + wm*32 + mt*16 + gid;
        #pragma unroll
        for (int nt = 0; nt < 8; nt++) {
            int col = bn + wn*64 + nt*8 + 2*tig;
            *(float2*)(C + (size_t)r0 * N + col)       = make_float2(acc[mt][nt][0], acc[mt][nt][1]);
            *(float2*)(C + (size_t)(r0 + 8) * N + col) = make_float2(acc[mt][nt][2], acc[mt][nt][3]);
        }
    }
}

// ---------------- mma.sync flash attention (causal, GQA) --------------------
// CTA: 256 threads (8 warps), BQ=128 (warp = 16 rows), BK=64.
#define QLD 132
#define PLD 68
#define QOFF 0
#define KOFF (128*QLD)
#define VOFF (KOFF + 64*QLD)
#define POFF (VOFF + 64*QLD)
#define FLASH_SMEM ((POFF + 128*PLD)*4)

__global__ __launch_bounds__(256) void flash_tc(
    const float* __restrict__ Q, const float* __restrict__ K,
    const float* __restrict__ V, float* __restrict__ AO)
{
    extern __shared__ uint32_t sm[];
    uint32_t* Qs = sm + QOFF;
    uint32_t* Ks = sm + KOFF;
    uint32_t* Vs = sm + VOFF;
    uint32_t* Ps = sm + POFF;

    const int tid = threadIdx.x;
    const int wid = tid >> 5, lane = tid & 31;
    const int gid = lane >> 2, tig = lane & 3;
    const int qt = blockIdx.x, h = blockIdx.y, b = blockIdx.z;
    const int hk = h >> 2;
    const int wrow = wid * 16;
    const int q0 = b*T_SEQ + qt*128;

    // load Q tile (pre-scaled, tf32)
    for (int i = tid; i < 128*32; i += 256) {
        int r = i >> 5, d4 = i & 31;
        float4 v = *(const float4*)(Q + (size_t)(q0 + r)*DMODEL + h*HD + d4*4);
        uint32_t* d = &Qs[r*QLD + d4*4];
        d[0] = cvt_tf32(v.x * FA_SCALE); d[1] = cvt_tf32(v.y * FA_SCALE);
        d[2] = cvt_tf32(v.z * FA_SCALE); d[3] = cvt_tf32(v.w * FA_SCALE);
    }

    float oacc[16][4];
    #pragma unroll
    for (int nt = 0; nt < 16; nt++)
        #pragma unroll
        for (int e = 0; e < 4; e++) oacc[nt][e] = 0.f;

    float l0 = 0.f, l1 = 0.f;
    const int nkt = 2*qt + 2;

    for (int kt = 0; kt < nkt; ++kt) {
        __syncthreads();   // previous iteration done reading K/V
        const int k0 = b*T_SEQ + kt*64;
        for (int i = tid; i < 64*32; i += 256) {
            int r = i >> 5, d4 = i & 31;
            float4 kv = *(const float4*)(K + (size_t)(k0 + r)*DKV + hk*HD + d4*4);
            float4 vv = *(const float4*)(V + (size_t)(k0 + r)*DKV + hk*HD + d4*4);
            uint32_t* dk = &Ks[r*QLD + d4*4];
            dk[0] = cvt_tf32(kv.x); dk[1] = cvt_tf32(kv.y);
            dk[2] = cvt_tf32(kv.z); dk[3] = cvt_tf32(kv.w);
            uint32_t* dv = &Vs[r*QLD + d4*4];
            dv[0] = cvt_tf32(vv.x); dv[1] = cvt_tf32(vv.y);
            dv[2] = cvt_tf32(vv.z); dv[3] = cvt_tf32(vv.w);
        }
        __syncthreads();

        // S = Q @ K^T : warp computes 16 x 64
        float sacc[8][4];
        #pragma unroll
        for (int nt = 0; nt < 8; nt++)
            #pragma unroll
            for (int e = 0; e < 4; e++) sacc[nt][e] = 0.f;

        #pragma unroll
        for (int ks = 0; ks < 16; ++ks) {
            uint32_t af[4];
            af[0] = Qs[(wrow + gid    )*QLD + ks*8 + tig];
            af[1] = Qs[(wrow + gid + 8)*QLD + ks*8 + tig];
            af[2] = Qs[(wrow + gid    )*QLD + ks*8 + tig + 4];
            af[3] = Qs[(wrow + gid + 8)*QLD + ks*8 + tig + 4];
            #pragma unroll
            for (int nt = 0; nt < 8; nt++) {
                uint32_t bf[2];
                bf[0] = Ks[(nt*8 + gid)*QLD + ks*8 + tig];
                bf[1] = Ks[(nt*8 + gid)*QLD + ks*8 + tig + 4];
                mma8(sacc[nt], af, bf);
            }
        }

        // softmax without max-subtraction; causal mask; P -> smem (tf32)
        const int qg0 = qt*128 + wrow + gid;     // row for e={0,1}
        const int kb  = kt*64;
        #pragma unroll
        for (int nt = 0; nt < 8; nt++) {
            int colb = nt*8 + 2*tig;
            #pragma unroll
            for (int e = 0; e < 4; e++) {
                int rloc = (e < 2) ? 0 : 8;
                int kcol = kb + colb + (e & 1);
                float p = (kcol <= qg0 + rloc) ? __expf(sacc[nt][e]) : 0.f;
                uint32_t pt = cvt_tf32(p);
                float pf = __uint_as_float(pt);
                if (e < 2) l0 += pf; else l1 += pf;
                Ps[(wrow + gid + rloc)*PLD + colb + (e & 1)] = pt;
            }
        }
        __syncwarp();   // warp re-reads only its own 16 P rows

        // O += P @ V : warp 16 x 128, k-dim 64
        #pragma unroll
        for (int ks = 0; ks < 8; ++ks) {
            uint32_t af[4];
            af[0] = Ps[(wrow + gid    )*PLD + ks*8 + tig];
            af[1] = Ps[(wrow + gid + 8)*PLD + ks*8 + tig];
            af[2] = Ps[(wrow + gid    )*PLD + ks*8 + tig + 4];
            af[3] = Ps[(wrow + gid + 8)*PLD + ks*8 + tig + 4];
            #pragma unroll
            for (int nt = 0; nt < 16; nt++) {
                uint32_t bf[2];
                bf[0] = Vs[(ks*8 + tig    )*QLD + nt*8 + gid];
                bf[1] = Vs[(ks*8 + tig + 4)*QLD + nt*8 + gid];
                mma8(oacc[nt], af, bf);
            }
        }
    }

    // reduce row sums across quad (lanes sharing gid)
    l0 += __shfl_xor_sync(0xffffffff, l0, 1);
    l0 += __shfl_xor_sync(0xffffffff, l0, 2);
    l1 += __shfl_xor_sync(0xffffffff, l1, 1);
    l1 += __shfl_xor_sync(0xffffffff, l1, 2);
    const float inv0 = 1.f / l0, inv1 = 1.f / l1;

    const int r0 = q0 + wrow + gid;
    #pragma unroll
    for (int nt = 0; nt < 16; nt++) {
        int col = h*HD + nt*8 + 2*tig;
        *(float2*)(AO + (size_t)r0 * DMODEL + col) =
            make_float2(oacc[nt][0]*inv0, oacc[nt][1]*inv0);
        *(float2*)(AO + (size_t)(r0 + 8) * DMODEL + col) =
            make_float2(oacc[nt][2]*inv1, oacc[nt][3]*inv1);
    }
}

// ---------------- launch -----------------------------------------------------
extern "C" void kernel_launch(void* const* d_in, const int* in_sizes, int n_in,
                              void* d_out, int out_size)
{
    const float* x  = (const float*)d_in[0];
    const float* Wq = (const float*)d_in[1];
    const float* Wk = (const float*)d_in[2];
    const float* Wv = (const float*)d_in[3];
    const float* Wo = (const float*)d_in[4];
    float* out = (float*)d_out;

    float *Q, *K, *V, *AO;
    cudaGetSymbolAddress((void**)&Q,  g_Q);
    cudaGetSymbolAddress((void**)&K,  g_K);
    cudaGetSymbolAddress((void**)&V,  g_V);
    cudaGetSymbolAddress((void**)&AO, g_AO);

    cudaFuncSetAttribute(flash_tc, cudaFuncAttributeMaxDynamicSharedMemorySize, FLASH_SMEM);

    rope_table_kernel<<<(T_SEQ*64 + 255)/256, 256>>>();

    tc_gemm<<<dim3(DMODEL/128, M_ROWS/128), 256>>>(x, Wq, Q, M_ROWS, DMODEL, DMODEL);
    tc_gemm<<<dim3(DKV/128,    M_ROWS/128), 256>>>(x, Wk, K, M_ROWS, DKV,    DMODEL);
    tc_gemm<<<dim3(DKV/128,    M_ROWS/128), 256>>>(x, Wv, V, M_ROWS, DKV,    DMODEL);

    rope_apply_kernel<<<(M_ROWS*HQ*64  + 255)/256, 256>>>(Q, HQ);
    rope_apply_kernel<<<(M_ROWS*HKV*64 + 255)/256, 256>>>(K, HKV);

    flash_tc<<<dim3(T_SEQ/128, HQ, BATCH), 256, FLASH_SMEM>>>(Q, K, V, AO);

    tc_gemm<<<dim3(DMODEL/128, M_ROWS/128), 256>>>(AO, Wo, out, M_ROWS, DMODEL, DMODEL);
}

// round 4
// speedup vs baseline: 4.6967x; 1.3141x over previous
#include <cuda_runtime.h>
#include <cuda_fp16.h>
#include <math.h>
#include <stdint.h>

#define T_SEQ 2048
#define BATCH 2
#define DMODEL 2048
#define HQ 16
#define HKV 4
#define HD 128
#define M_ROWS (BATCH*T_SEQ)   /* 4096 */
#define DKV (HKV*HD)           /* 512 */
#define FA_SCALE 0.08838834764831845f

// ---------------- scratch ---------------------------------------------------
__device__ float  g_Q[M_ROWS*DMODEL];
__device__ float  g_K[M_ROWS*DKV];
__device__ float  g_V[M_ROWS*DKV];
__device__ float  g_AO[M_ROWS*DMODEL];
__device__ __half g_Qh[M_ROWS*DMODEL];
__device__ __half g_Kh[M_ROWS*DKV];
__device__ __half g_Vh[M_ROWS*DKV];
__device__ float  g_cos[T_SEQ*64];
__device__ float  g_sin[T_SEQ*64];

// ---------------- helpers ----------------------------------------------------
__device__ __forceinline__ uint32_t f2h2(float a, float b) {
    __half2 h = __halves2half2(__float2half_rn(a), __float2half_rn(b));
    return *reinterpret_cast<uint32_t*>(&h);
}
// D(16x8) += A(16x16,row) * B(16x8,col) ; fp16 in, fp32 accum
__device__ __forceinline__ void mma16(float* d, const uint32_t* a, const uint32_t* b) {
    asm volatile("mma.sync.aligned.m16n8k16.row.col.f32.f16.f16.f32 "
        "{%0,%1,%2,%3}, {%4,%5,%6,%7}, {%8,%9}, {%0,%1,%2,%3};"
        : "+f"(d[0]), "+f"(d[1]), "+f"(d[2]), "+f"(d[3])
        : "r"(a[0]), "r"(a[1]), "r"(a[2]), "r"(a[3]), "r"(b[0]), "r"(b[1]));
}

// ---------------- RoPE ------------------------------------------------------
__global__ void rope_table_kernel() {
    int idx = blockIdx.x*blockDim.x + threadIdx.x;
    if (idx >= T_SEQ*64) return;
    int t = idx >> 6, i = idx & 63;
    float inv = powf(10000.0f, -(float)i / 64.0f);
    float ang = (float)t * inv;
    g_cos[idx] = (float)cos((double)ang);
    g_sin[idx] = (float)sin((double)ang);
}

// read fp32, apply RoPE, write fp16 (optionally pre-scaled)
__global__ void rope_half_kernel(const float* __restrict__ src, __half* __restrict__ dst,
                                 int heads, float scale) {
    int idx = blockIdx.x*blockDim.x + threadIdx.x;
    int total = M_ROWS * heads * 32;
    if (idx >= total) return;
    int i2 = idx & 31;               // pair-of-dims index (dims 2*i2, 2*i2+1)
    int h = (idx >> 5) % heads;
    int m = idx / (32 * heads);
    int t = m & (T_SEQ - 1);
    int d0 = 2*i2;
    const float* p = src + (size_t)m * heads * HD + h * HD;
    float a0 = p[d0], a1 = p[d0+1], b0 = p[d0+64], b1 = p[d0+65];
    float c0 = g_cos[t*64 + d0], c1 = g_cos[t*64 + d0 + 1];
    float s0 = g_sin[t*64 + d0], s1 = g_sin[t*64 + d0 + 1];
    float lo0 = (a0*c0 - b0*s0) * scale;
    float lo1 = (a1*c1 - b1*s1) * scale;
    float hi0 = (b0*c0 + a0*s0) * scale;
    float hi1 = (b1*c1 + a1*s1) * scale;
    uint32_t* q = (uint32_t*)(dst + (size_t)m * heads * HD + h * HD);
    q[i2]      = f2h2(lo0, lo1);
    q[32 + i2] = f2h2(hi0, hi1);
}

__global__ void v_half_kernel(const float* __restrict__ src, __half* __restrict__ dst) {
    int i = blockIdx.x*blockDim.x + threadIdx.x;
    if (i >= M_ROWS*DKV/4) return;
    float4 v = *(const float4*)(src + (size_t)i*4);
    uint2 u; u.x = f2h2(v.x, v.y); u.y = f2h2(v.z, v.w);
    *(uint2*)(dst + (size_t)i*4) = u;
}

// ---------------- fp16 mma.sync GEMM ----------------------------------------
// C[M,N] = A[M,K] @ B[K,N]. 128x128 CTA tile, 8 warps (4x2), warp tile 32x64.
// K-chunk 32. Column-tile dispatch over up to 3 (B, C) pairs (fused QKV).
__global__ __launch_bounds__(256) void tc_gemm_h(
    const float* __restrict__ A,
    const float* __restrict__ B0, const float* __restrict__ B1, const float* __restrict__ B2,
    float* __restrict__ C0, float* __restrict__ C1, float* __restrict__ C2,
    int t0, int t1, int K)
{
    __shared__ uint32_t As[128][20];   // [m][k/2] fp16 pairs, pad 4
    __shared__ uint32_t Bs[128][20];   // [n][k/2]

    const int tx = blockIdx.x;
    const float* B; float* C; int N; int cb;
    if (tx < t0)           { B = B0; C = C0; N = t0*128; cb = tx*128; }
    else if (tx < t0 + t1) { B = B1; C = C1; N = t1*128; cb = (tx - t0)*128; }
    else                   { B = B2; C = C2; N = (gridDim.x - t0 - t1)*128; cb = (tx - t0 - t1)*128; }

    const int tid = threadIdx.x;
    const int wid = tid >> 5, lane = tid & 31;
    const int gid = lane >> 2, tig = lane & 3;
    const int wm = wid & 3, wn = wid >> 2;
    const int bm = blockIdx.y * 128;
    const int nc = K >> 5;

    float acc[2][8][4];
    #pragma unroll
    for (int mt = 0; mt < 2; mt++)
        #pragma unroll
        for (int nt = 0; nt < 8; nt++)
            #pragma unroll
            for (int e = 0; e < 4; e++) acc[mt][nt][e] = 0.f;

    // prefetch registers
    float4 pa[4], pb[2][2];
    const int ar = tid >> 3, ac4 = tid & 7;       // A rows ar+32i, float4 col ac4
    const int bkp = tid >> 5, bn4 = tid & 31;     // B k-pairs 2bkp(+16i), float4 col bn4

    #pragma unroll
    for (int i = 0; i < 4; i++)
        pa[i] = *(const float4*)(A + (size_t)(bm + ar + 32*i) * K + ac4*4);
    #pragma unroll
    for (int i = 0; i < 2; i++)
        #pragma unroll
        for (int j = 0; j < 2; j++)
            pb[i][j] = *(const float4*)(B + (size_t)(16*i + 2*bkp + j) * N + cb + bn4*4);

    for (int c = 0; c < nc; ++c) {
        #pragma unroll
        for (int i = 0; i < 4; i++) {
            uint2 u; u.x = f2h2(pa[i].x, pa[i].y); u.y = f2h2(pa[i].z, pa[i].w);
            *(uint2*)&As[ar + 32*i][ac4*2] = u;
        }
        #pragma unroll
        for (int i = 0; i < 2; i++) {
            Bs[bn4*4 + 0][8*i + bkp] = f2h2(pb[i][0].x, pb[i][1].x);
            Bs[bn4*4 + 1][8*i + bkp] = f2h2(pb[i][0].y, pb[i][1].y);
            Bs[bn4*4 + 2][8*i + bkp] = f2h2(pb[i][0].z, pb[i][1].z);
            Bs[bn4*4 + 3][8*i + bkp] = f2h2(pb[i][0].w, pb[i][1].w);
        }
        __syncthreads();

        if (c + 1 < nc) {
            const int ko = (c + 1) << 5;
            #pragma unroll
            for (int i = 0; i < 4; i++)
                pa[i] = *(const float4*)(A + (size_t)(bm + ar + 32*i) * K + ko + ac4*4);
            #pragma unroll
            for (int i = 0; i < 2; i++)
                #pragma unroll
                for (int j = 0; j < 2; j++)
                    pb[i][j] = *(const float4*)(B + (size_t)(ko + 16*i + 2*bkp + j) * N + cb + bn4*4);
        }

        #pragma unroll
        for (int ks = 0; ks < 2; ++ks) {
            uint32_t af[2][4];
            #pragma unroll
            for (int mt = 0; mt < 2; mt++) {
                int r0 = wm*32 + mt*16 + gid;
                af[mt][0] = As[r0    ][ks*8 + tig];
                af[mt][1] = As[r0 + 8][ks*8 + tig];
                af[mt][2] = As[r0    ][ks*8 + tig + 4];
                af[mt][3] = As[r0 + 8][ks*8 + tig + 4];
            }
            #pragma unroll
            for (int nt = 0; nt < 8; nt++) {
                int col = wn*64 + nt*8 + gid;
                uint32_t bf[2];
                bf[0] = Bs[col][ks*8 + tig];
                bf[1] = Bs[col][ks*8 + tig + 4];
                #pragma unroll
                for (int mt = 0; mt < 2; mt++)
                    mma16(acc[mt][nt], af[mt], bf);
            }
        }
        __syncthreads();
    }

    #pragma unroll
    for (int mt = 0; mt < 2; mt++) {
        int r0 = bm + wm*32 + mt*16 + gid;
        #pragma unroll
        for (int nt = 0; nt < 8; nt++) {
            int col = cb + wn*64 + nt*8 + 2*tig;
            *(float2*)(C + (size_t)r0 * N + col)       = make_float2(acc[mt][nt][0], acc[mt][nt][1]);
            *(float2*)(C + (size_t)(r0 + 8) * N + col) = make_float2(acc[mt][nt][2], acc[mt][nt][3]);
        }
    }
}

// ---------------- fp16 mma.sync flash attention (causal, GQA) ---------------
// 256 threads (8 warps), BQ=128 (warp = 16 rows), BK=64.
#define QPITCH 68
#define VPITCH 36
#define FLASH_SMEM ((128*QPITCH + 64*QPITCH + 128*VPITCH + 128*VPITCH)*4)

__global__ __launch_bounds__(256) void flash_h(
    const __half* __restrict__ Qh, const __half* __restrict__ Kh,
    const __half* __restrict__ Vh, float* __restrict__ AO)
{
    extern __shared__ uint32_t smf[];
    uint32_t (*Qs)[QPITCH] = (uint32_t(*)[QPITCH])smf;
    uint32_t (*Ks)[QPITCH] = (uint32_t(*)[QPITCH])(smf + 128*QPITCH);
    uint32_t (*Vs)[VPITCH] = (uint32_t(*)[VPITCH])(smf + 128*QPITCH + 64*QPITCH);
    uint32_t (*Ps)[VPITCH] = (uint32_t(*)[VPITCH])(smf + 128*QPITCH + 64*QPITCH + 128*VPITCH);

    const int tid = threadIdx.x;
    const int wid = tid >> 5, lane = tid & 31;
    const int gid = lane >> 2, tig = lane & 3;
    const int qt = 15 - blockIdx.x;          // big tiles first
    const int h = blockIdx.y, b = blockIdx.z;
    const int hk = h >> 2;
    const int wrow = wid * 16;
    const int q0 = b*T_SEQ + qt*128;

    // Q tile (fp16, already scaled): 128 rows x 16 uint4
    for (int i = tid; i < 128*16; i += 256) {
        int r = i >> 4, c4 = i & 15;
        uint4 v = *(const uint4*)(Qh + (size_t)(q0 + r)*DMODEL + h*HD + c4*8);
        *(uint4*)&Qs[r][c4*4] = v;
    }

    float oacc[16][4];
    #pragma unroll
    for (int nt = 0; nt < 16; nt++)
        #pragma unroll
        for (int e = 0; e < 4; e++) oacc[nt][e] = 0.f;

    float l0 = 0.f, l1 = 0.f;
    const int nkt = 2*qt + 2;

    for (int kt = 0; kt < nkt; ++kt) {
        __syncthreads();
        const int k0 = b*T_SEQ + kt*64;
        // K: 64 rows x 16 uint4
        for (int i = tid; i < 64*16; i += 256) {
            int r = i >> 4, c4 = i & 15;
            uint4 v = *(const uint4*)(Kh + (size_t)(k0 + r)*DKV + hk*HD + c4*8);
            *(uint4*)&Ks[r][c4*4] = v;
        }
        // V transposed: Vs[d][jpair] = half2(V[2jp][d], V[2jp+1][d])
        for (int i = tid; i < 512; i += 256) {
            int jp = i & 31, d8 = i >> 5;
            uint4 va = *(const uint4*)(Vh + (size_t)(k0 + 2*jp    )*DKV + hk*HD + d8*8);
            uint4 vb = *(const uint4*)(Vh + (size_t)(k0 + 2*jp + 1)*DKV + hk*HD + d8*8);
            const __half* ah = (const __half*)&va;
            const __half* bh = (const __half*)&vb;
            #pragma unroll
            for (int t = 0; t < 8; t++)
                Vs[d8*8 + t][jp] = f2h2(__half2float(ah[t]), __half2float(bh[t]));
        }
        __syncthreads();

        // S = Q @ K^T : warp 16 x 64, k=128 (8 k-steps of 16)
        float sacc[8][4];
        #pragma unroll
        for (int nt = 0; nt < 8; nt++)
            #pragma unroll
            for (int e = 0; e < 4; e++) sacc[nt][e] = 0.f;

        #pragma unroll
        for (int ks = 0; ks < 8; ++ks) {
            uint32_t af[4];
            af[0] = Qs[wrow + gid    ][ks*8 + tig];
            af[1] = Qs[wrow + gid + 8][ks*8 + tig];
            af[2] = Qs[wrow + gid    ][ks*8 + tig + 4];
            af[3] = Qs[wrow + gid + 8][ks*8 + tig + 4];
            #pragma unroll
            for (int nt = 0; nt < 8; nt++) {
                uint32_t bf[2];
                bf[0] = Ks[nt*8 + gid][ks*8 + tig];
                bf[1] = Ks[nt*8 + gid][ks*8 + tig + 4];
                mma16(sacc[nt], af, bf);
            }
        }

        // softmax (no max-subtraction), causal mask, P -> smem (fp16)
        const int qg0 = qt*128 + wrow + gid;
        const int kb  = kt*64;
        #pragma unroll
        for (int nt = 0; nt < 8; nt++) {
            int colb = nt*8 + 2*tig;
            float p0 = (kb + colb     <= qg0    ) ? __expf(sacc[nt][0]) : 0.f;
            float p1 = (kb + colb + 1 <= qg0    ) ? __expf(sacc[nt][1]) : 0.f;
            float p2 = (kb + colb     <= qg0 + 8) ? __expf(sacc[nt][2]) : 0.f;
            float p3 = (kb + colb + 1 <= qg0 + 8) ? __expf(sacc[nt][3]) : 0.f;
            __half h0 = __float2half_rn(p0), h1 = __float2half_rn(p1);
            __half h2v = __float2half_rn(p2), h3 = __float2half_rn(p3);
            l0 += __half2float(h0) + __half2float(h1);
            l1 += __half2float(h2v) + __half2float(h3);
            __half2 lo = __halves2half2(h0, h1), hi = __halves2half2(h2v, h3);
            Ps[wrow + gid    ][nt*4 + tig] = *(uint32_t*)&lo;
            Ps[wrow + gid + 8][nt*4 + tig] = *(uint32_t*)&hi;
        }
        __syncwarp();

        // O += P @ V : warp 16 x 128, k=64 (4 k-steps of 16)
        #pragma unroll
        for (int ks = 0; ks < 4; ++ks) {
            uint32_t af[4];
            af[0] = Ps[wrow + gid    ][ks*8 + tig];
            af[1] = Ps[wrow + gid + 8][ks*8 + tig];
            af[2] = Ps[wrow + gid    ][ks*8 + tig + 4];
            af[3] = Ps[wrow + gid + 8][ks*8 + tig + 4];
            #pragma unroll
            for (int nt = 0; nt < 16; nt++) {
                uint32_t bf[2];
                bf[0] = Vs[nt*8 + gid][ks*8 + tig];
                bf[1] = Vs[nt*8 + gid][ks*8 + tig + 4];
                mma16(oacc[nt], af, bf);
            }
        }
    }

    l0 += __shfl_xor_sync(0xffffffff, l0, 1);
    l0 += __shfl_xor_sync(0xffffffff, l0, 2);
    l1 += __shfl_xor_sync(0xffffffff, l1, 1);
    l1 += __shfl_xor_sync(0xffffffff, l1, 2);
    const float inv0 = 1.f / l0, inv1 = 1.f / l1;

    const int r0 = q0 + wrow + gid;
    #pragma unroll
    for (int nt = 0; nt < 16; nt++) {
        int col = h*HD + nt*8 + 2*tig;
        *(float2*)(AO + (size_t)r0 * DMODEL + col) =
            make_float2(oacc[nt][0]*inv0, oacc[nt][1]*inv0);
        *(float2*)(AO + (size_t)(r0 + 8) * DMODEL + col) =
            make_float2(oacc[nt][2]*inv1, oacc[nt][3]*inv1);
    }
}

// ---------------- launch -----------------------------------------------------
extern "C" void kernel_launch(void* const* d_in, const int* in_sizes, int n_in,
                              void* d_out, int out_size)
{
    const float* x  = (const float*)d_in[0];
    const float* Wq = (const float*)d_in[1];
    const float* Wk = (const float*)d_in[2];
    const float* Wv = (const float*)d_in[3];
    const float* Wo = (const float*)d_in[4];
    float* out = (float*)d_out;

    float *Q, *K, *V, *AO;
    __half *Qh, *Kh, *Vh;
    cudaGetSymbolAddress((void**)&Q,  g_Q);
    cudaGetSymbolAddress((void**)&K,  g_K);
    cudaGetSymbolAddress((void**)&V,  g_V);
    cudaGetSymbolAddress((void**)&AO, g_AO);
    cudaGetSymbolAddress((void**)&Qh, g_Qh);
    cudaGetSymbolAddress((void**)&Kh, g_Kh);
    cudaGetSymbolAddress((void**)&Vh, g_Vh);

    cudaFuncSetAttribute(flash_h, cudaFuncAttributeMaxDynamicSharedMemorySize, FLASH_SMEM);

    rope_table_kernel<<<(T_SEQ*64 + 255)/256, 256>>>();

    // fused QKV projection: column tiles 0-15 -> Wq/Q, 16-19 -> Wk/K, 20-23 -> Wv/V
    tc_gemm_h<<<dim3(24, M_ROWS/128), 256>>>(x, Wq, Wk, Wv, Q, K, V, 16, 4, DMODEL);

    rope_half_kernel<<<(M_ROWS*HQ*32  + 255)/256, 256>>>(Q, Qh, HQ, FA_SCALE);
    rope_half_kernel<<<(M_ROWS*HKV*32 + 255)/256, 256>>>(K, Kh, HKV, 1.0f);
    v_half_kernel<<<(M_ROWS*DKV/4 + 255)/256, 256>>>(V, Vh);

    flash_h<<<dim3(16, HQ, BATCH), 256, FLASH_SMEM>>>(Qh, Kh, Vh, AO);

    // output projection
    tc_gemm_h<<<dim3(16, M_ROWS/128), 256>>>(AO, Wo, Wo, Wo, out, out, out, 16, 0, DMODEL);
}

// round 6
// speedup vs baseline: 10.5317x; 2.2424x over previous
#include <cuda_runtime.h>
#include <cuda_fp16.h>
#include <math.h>
#include <stdint.h>

#define T_SEQ 2048
#define BATCH 2
#define DMODEL 2048
#define HQ 16
#define HKV 4
#define HD 128
#define M_ROWS (BATCH*T_SEQ)   /* 4096 */
#define DKV (HKV*HD)           /* 512 */
#define FA_SCALE 0.08838834764831845f

// ---------------- scratch ---------------------------------------------------
__device__ float  g_Q[M_ROWS*DMODEL];
__device__ float  g_K[M_ROWS*DKV];
__device__ float  g_V[M_ROWS*DKV];
__device__ __half g_xh[M_ROWS*DMODEL];
__device__ __half g_Wqh[DMODEL*DMODEL];
__device__ __half g_Wkh[DMODEL*DKV];
__device__ __half g_Wvh[DMODEL*DKV];
__device__ __half g_Woh[DMODEL*DMODEL];
__device__ __half g_Qh[M_ROWS*DMODEL];
__device__ __half g_Kh[M_ROWS*DKV];
__device__ __half g_Vh[M_ROWS*DKV];
__device__ __half g_AOh[M_ROWS*DMODEL];
__device__ float  g_cos[T_SEQ*64];
__device__ float  g_sin[T_SEQ*64];

// ---------------- helpers ----------------------------------------------------
__device__ __forceinline__ uint32_t f2h2(float a, float b) {
    __half2 h = __halves2half2(__float2half_rn(a), __float2half_rn(b));
    return *reinterpret_cast<uint32_t*>(&h);
}
__device__ __forceinline__ uint32_t cvta_smem(const void* p) {
    uint32_t a;
    asm("{ .reg .u64 t; cvta.to.shared.u64 t, %1; cvt.u32.u64 %0, t; }"
        : "=r"(a) : "l"(p));
    return a;
}
__device__ __forceinline__ void mma16(float* d, const uint32_t* a, const uint32_t* b) {
    asm volatile("mma.sync.aligned.m16n8k16.row.col.f32.f16.f16.f32 "
        "{%0,%1,%2,%3}, {%4,%5,%6,%7}, {%8,%9}, {%0,%1,%2,%3};"
        : "+f"(d[0]), "+f"(d[1]), "+f"(d[2]), "+f"(d[3])
        : "r"(a[0]), "r"(a[1]), "r"(a[2]), "r"(a[3]), "r"(b[0]), "r"(b[1]));
}
__device__ __forceinline__ void ldsm4(uint32_t* r, uint32_t a) {
    asm volatile("ldmatrix.sync.aligned.m8n8.x4.shared.b16 {%0,%1,%2,%3}, [%4];"
        : "=r"(r[0]), "=r"(r[1]), "=r"(r[2]), "=r"(r[3]) : "r"(a));
}
__device__ __forceinline__ void ldsm4t(uint32_t* r, uint32_t a) {
    asm volatile("ldmatrix.sync.aligned.m8n8.x4.trans.shared.b16 {%0,%1,%2,%3}, [%4];"
        : "=r"(r[0]), "=r"(r[1]), "=r"(r[2]), "=r"(r[3]) : "r"(a));
}
__device__ __forceinline__ void cp16(uint32_t dst, const void* src) {
    asm volatile("cp.async.cg.shared.global [%0], [%1], 16;" :: "r"(dst), "l"(src));
}
#define CPCOMMIT() asm volatile("cp.async.commit_group;" ::: "memory")
#define CPWAIT1()  asm volatile("cp.async.wait_group 1;" ::: "memory")
#define CPWAIT0()  asm volatile("cp.async.wait_group 0;" ::: "memory")

// ---------------- input conversion fp32 -> fp16 ------------------------------
#define N_X  ((long)M_ROWS*DMODEL/4)
#define N_WQ ((long)DMODEL*DMODEL/4)
#define N_WK ((long)DMODEL*DKV/4)
#define CONV_TOTAL (N_X + 2*N_WQ + 2*N_WK)

__global__ void conv_all(const float* __restrict__ x, const float* __restrict__ wq,
                         const float* __restrict__ wk, const float* __restrict__ wv,
                         const float* __restrict__ wo) {
    long i = (long)blockIdx.x*256 + threadIdx.x;
    const float* src; __half* dst; long off;
    if (i < N_X)                       { src = x;  dst = g_xh;  off = i; }
    else if (i < N_X + N_WQ)           { src = wq; dst = g_Wqh; off = i - N_X; }
    else if (i < N_X + N_WQ + N_WK)    { src = wk; dst = g_Wkh; off = i - N_X - N_WQ; }
    else if (i < N_X + N_WQ + 2*N_WK)  { src = wv; dst = g_Wvh; off = i - N_X - N_WQ - N_WK; }
    else if (i < CONV_TOTAL)           { src = wo; dst = g_Woh; off = i - N_X - N_WQ - 2*N_WK; }
    else return;
    float4 v = *(const float4*)(src + off*4);
    uint2 u; u.x = f2h2(v.x, v.y); u.y = f2h2(v.z, v.w);
    *(uint2*)(dst + off*4) = u;
}

// ---------------- RoPE ------------------------------------------------------
__global__ void rope_table_kernel() {
    int idx = blockIdx.x*blockDim.x + threadIdx.x;
    if (idx >= T_SEQ*64) return;
    int t = idx >> 6, i = idx & 63;
    float inv = powf(10000.0f, -(float)i / 64.0f);
    float ang = (float)t * inv;
    g_cos[idx] = (float)cos((double)ang);
    g_sin[idx] = (float)sin((double)ang);
}

__global__ void rope_half_kernel(const float* __restrict__ src, __half* __restrict__ dst,
                                 int heads, float scale) {
    int idx = blockIdx.x*blockDim.x + threadIdx.x;
    int total = M_ROWS * heads * 32;
    if (idx >= total) return;
    int i2 = idx & 31;
    int h = (idx >> 5) % heads;
    int m = idx / (32 * heads);
    int t = m & (T_SEQ - 1);
    int d0 = 2*i2;
    const float* p = src + (size_t)m * heads * HD + h * HD;
    float a0 = p[d0], a1 = p[d0+1], b0 = p[d0+64], b1 = p[d0+65];
    float c0 = g_cos[t*64 + d0], c1 = g_cos[t*64 + d0 + 1];
    float s0 = g_sin[t*64 + d0], s1 = g_sin[t*64 + d0 + 1];
    uint32_t* q = (uint32_t*)(dst + (size_t)m * heads * HD + h * HD);
    q[i2]      = f2h2((a0*c0 - b0*s0)*scale, (a1*c1 - b1*s1)*scale);
    q[32 + i2] = f2h2((b0*c0 + a0*s0)*scale, (b1*c1 + a1*s1)*scale);
}

__global__ void v_half_kernel(const float* __restrict__ src, __half* __restrict__ dst) {
    int i = blockIdx.x*blockDim.x + threadIdx.x;
    if (i >= M_ROWS*DKV/4) return;
    float4 v = *(const float4*)(src + (size_t)i*4);
    uint2 u; u.x = f2h2(v.x, v.y); u.y = f2h2(v.z, v.w);
    *(uint2*)(dst + (size_t)i*4) = u;
}

// ---------------- fp16 GEMM: cp.async 3-stage + ldmatrix ---------------------
// C[M,N](fp32) = A[M,K](fp16) @ B[K,N](fp16). 128x128 CTA, 8 warps (4x2), BK=64.
#define GSTB 32768
#define GEMM_SMEM (3*GSTB)

__global__ __launch_bounds__(256) void hgemm(
    const __half* __restrict__ A,
    const __half* __restrict__ B0, const __half* __restrict__ B1, const __half* __restrict__ B2,
    float* __restrict__ C0, float* __restrict__ C1, float* __restrict__ C2,
    int t0, int t1, int K)
{
    extern __shared__ char gsm[];
    const uint32_t sb = cvta_smem(gsm);

    const int tx = blockIdx.x;
    const __half* B; float* C; int N, cb;
    if (tx < t0)           { B = B0; C = C0; N = t0*128; cb = tx*128; }
    else if (tx < t0 + t1) { B = B1; C = C1; N = t1*128; cb = (tx - t0)*128; }
    else { B = B2; C = C2; N = ((int)gridDim.x - t0 - t1)*128; cb = (tx - t0 - t1)*128; }

    const int tid = threadIdx.x;
    const int lane = tid & 31, wid = tid >> 5;
    const int gid = lane >> 2, tig = lane & 3;
    const int wm = wid & 3, wn = wid >> 2;
    const int bm = blockIdx.y * 128;
    const int nc = K >> 6;

    const int ar = tid >> 3, ac = tid & 7;
    const int bk = tid >> 4, bc = tid & 15;
    const uint32_t aswz = (uint32_t)(ac ^ (ar & 7)) << 4;
    const uint32_t bswz = (uint32_t)((bc & 8) | ((bc ^ (bk & 7)) & 7)) << 4;

    auto issue = [&](int c) {
        const uint32_t sA = sb + (c % 3)*GSTB;
        const uint32_t sB = sA + 16384;
        const __half* Ag = A + (size_t)(bm + ar)*K + c*64 + ac*8;
        #pragma unroll
        for (int i = 0; i < 4; i++)
            cp16(sA + (uint32_t)(ar + 32*i)*128 + aswz, Ag + (size_t)(32*i)*K);
        const __half* Bg = B + (size_t)(c*64 + bk)*N + cb + bc*8;
        #pragma unroll
        for (int i = 0; i < 4; i++)
            cp16(sB + (uint32_t)(bk + 16*i)*256 + bswz, Bg + (size_t)(16*i)*N);
        CPCOMMIT();
    };

    float acc[2][8][4];
    #pragma unroll
    for (int mt = 0; mt < 2; mt++)
        #pragma unroll
        for (int nt = 0; nt < 8; nt++)
            #pragma unroll
            for (int e = 0; e < 4; e++) acc[mt][nt][e] = 0.f;

    issue(0); issue(1);

    for (int c = 0; c < nc; ++c) {
        if (c + 2 < nc) { CPWAIT1(); } else { CPWAIT0(); }
        __syncthreads();
        if (c + 2 < nc) issue(c + 2);

        const uint32_t sA = sb + (c % 3)*GSTB;
        const uint32_t sB = sA + 16384;

        #pragma unroll
        for (int ks = 0; ks < 4; ++ks) {
            uint32_t af[2][4];
            #pragma unroll
            for (int mt = 0; mt < 2; mt++) {
                int row = wm*32 + mt*16 + (lane & 15);
                int ch = ks*2 + (lane >> 4);
                ldsm4(af[mt], sA + (uint32_t)row*128 + ((uint32_t)(ch ^ (row & 7)) << 4));
            }
            uint32_t bf[8][2];
            #pragma unroll
            for (int nb = 0; nb < 4; nb++) {
                int kr = ks*16 + (lane & 15);
                int ch = wn*8 + nb*2 + (lane >> 4);
                uint32_t q[4];
                ldsm4t(q, sB + (uint32_t)kr*256 +
                          ((uint32_t)((ch & 8) | ((ch ^ (kr & 7)) & 7)) << 4));
                bf[2*nb][0] = q[0]; bf[2*nb][1] = q[1];
                bf[2*nb+1][0] = q[2]; bf[2*nb+1][1] = q[3];
            }
            #pragma unroll
            for (int mt = 0; mt < 2; mt++)
                #pragma unroll
                for (int nt = 0; nt < 8; nt++)
                    mma16(acc[mt][nt], af[mt], bf[nt]);
        }
    }

    #pragma unroll
    for (int mt = 0; mt < 2; mt++) {
        int r0 = bm + wm*32 + mt*16 + gid;
        #pragma unroll
        for (int nt = 0; nt < 8; nt++) {
            int col = cb + wn*64 + nt*8 + 2*tig;
            *(float2*)(C + (size_t)r0 * N + col)       = make_float2(acc[mt][nt][0], acc[mt][nt][1]);
            *(float2*)(C + (size_t)(r0 + 8) * N + col) = make_float2(acc[mt][nt][2], acc[mt][nt][3]);
        }
    }
}

// ---------------- flash attention: ldmatrix + cp.async, P in registers -------
// 256 threads (8 warps), BQ=128 (warp = 16 rows), BK=64.
// SMEM: Q 32KB @0 ; THREE stages of (K 16KB + V 16KB) @32KB  (stages >= distance+1!)
#define FKVSTB 32768
#define FLASH_SMEM (32768 + 3*FKVSTB)

__global__ __launch_bounds__(256) void flash_h2(
    const __half* __restrict__ Qh, const __half* __restrict__ Kh,
    const __half* __restrict__ Vh, __half* __restrict__ AOh)
{
    extern __shared__ char fsm[];
    const uint32_t sb = cvta_smem(fsm);
    const int tid = threadIdx.x, lane = tid & 31, wid = tid >> 5;
    const int gid = lane >> 2, tig = lane & 3;
    const int qt = 15 - blockIdx.x;
    const int h = blockIdx.y, b = blockIdx.z;
    const int hk = h >> 2;
    const int wrow = wid * 16;
    const int q0 = b*T_SEQ + qt*128;
    const int nkt = 2*qt + 2;

    auto issue_kv = [&](int kt) {
        const uint32_t sK = sb + 32768 + (kt % 3)*FKVSTB;
        const uint32_t sV = sK + 16384;
        const int k0g = b*T_SEQ + kt*64;
        const __half* Kg = Kh + (size_t)k0g*DKV + hk*HD;
        const __half* Vg = Vh + (size_t)k0g*DKV + hk*HD;
        #pragma unroll
        for (int i = 0; i < 4; i++) {
            int id = tid + 256*i;
            int r = id >> 4, c = id & 15;
            uint32_t o = (uint32_t)r*256 + ((uint32_t)((c & 8) | ((c ^ (r & 7)) & 7)) << 4);
            cp16(sK + o, Kg + (size_t)r*DKV + c*8);
            cp16(sV + o, Vg + (size_t)r*DKV + c*8);
        }
        CPCOMMIT();
    };

    // group 0: Q tile + KV(0); group 1: KV(1)
    {
        const __half* Qg = Qh + (size_t)q0*DMODEL + h*HD;
        #pragma unroll
        for (int i = 0; i < 8; i++) {
            int id = tid + 256*i;
            int r = id >> 4, c = id & 15;
            uint32_t o = (uint32_t)r*256 + ((uint32_t)((c & 8) | ((c ^ (r & 7)) & 7)) << 4);
            cp16(sb + o, Qg + (size_t)r*DMODEL + c*8);
        }
        const __half* Kg = Kh + (size_t)(b*T_SEQ)*DKV + hk*HD;
        const __half* Vg = Vh + (size_t)(b*T_SEQ)*DKV + hk*HD;
        const uint32_t sK = sb + 32768, sV = sK + 16384;
        #pragma unroll
        for (int i = 0; i < 4; i++) {
            int id = tid + 256*i;
            int r = id >> 4, c = id & 15;
            uint32_t o = (uint32_t)r*256 + ((uint32_t)((c & 8) | ((c ^ (r & 7)) & 7)) << 4);
            cp16(sK + o, Kg + (size_t)r*DKV + c*8);
            cp16(sV + o, Vg + (size_t)r*DKV + c*8);
        }
        CPCOMMIT();
        issue_kv(1);
    }

    float oacc[16][4];
    #pragma unroll
    for (int nt = 0; nt < 16; nt++)
        #pragma unroll
        for (int e = 0; e < 4; e++) oacc[nt][e] = 0.f;
    float l0 = 0.f, l1 = 0.f;

    for (int kt = 0; kt < nkt; ++kt) {
        if (kt + 2 < nkt) { CPWAIT1(); } else { CPWAIT0(); }
        __syncthreads();
        if (kt + 2 < nkt) issue_kv(kt + 2);

        const uint32_t sK = sb + 32768 + (kt % 3)*FKVSTB;
        const uint32_t sV = sK + 16384;

        // S = Q @ K^T : warp 16x64, k=128
        float sacc[8][4];
        #pragma unroll
        for (int nt = 0; nt < 8; nt++)
            #pragma unroll
            for (int e = 0; e < 4; e++) sacc[nt][e] = 0.f;

        #pragma unroll
        for (int ks = 0; ks < 8; ++ks) {
            uint32_t af[4];
            {
                int row = wrow + (lane & 15);
                int ch = ks*2 + (lane >> 4);
                ldsm4(af, sb + (uint32_t)row*256 +
                          ((uint32_t)((ch & 8) | ((ch ^ (row & 7)) & 7)) << 4));
            }
            #pragma unroll
            for (int np = 0; np < 4; np++) {
                int row = np*16 + (lane & 15);
                int ch = ks*2 + (lane >> 4);
                uint32_t q[4];
                ldsm4(q, sK + (uint32_t)row*256 +
                          ((uint32_t)((ch & 8) | ((ch ^ (row & 7)) & 7)) << 4));
                uint32_t bf0[2] = {q[0], q[2]}, bf1[2] = {q[1], q[3]};
                mma16(sacc[2*np],   af, bf0);
                mma16(sacc[2*np+1], af, bf1);
            }
        }

        // mask + exp + pack P into A-fragments (registers only)
        const int qg0 = qt*128 + wrow + gid;
        const int kb  = kt*64;
        uint32_t pf[4][4];
        #pragma unroll
        for (int k2 = 0; k2 < 4; ++k2) {
            float p[2][4];
            #pragma unroll
            for (int j = 0; j < 2; j++) {
                int nt = 2*k2 + j;
                int c0 = kb + nt*8 + 2*tig;
                p[j][0] = (c0     <= qg0    ) ? __expf(sacc[nt][0]) : 0.f;
                p[j][1] = (c0 + 1 <= qg0    ) ? __expf(sacc[nt][1]) : 0.f;
                p[j][2] = (c0     <= qg0 + 8) ? __expf(sacc[nt][2]) : 0.f;
                p[j][3] = (c0 + 1 <= qg0 + 8) ? __expf(sacc[nt][3]) : 0.f;
            }
            pf[k2][0] = f2h2(p[0][0], p[0][1]);
            pf[k2][1] = f2h2(p[0][2], p[0][3]);
            pf[k2][2] = f2h2(p[1][0], p[1][1]);
            pf[k2][3] = f2h2(p[1][2], p[1][3]);
            float2 t;
            t = __half22float2(*(__half2*)&pf[k2][0]); l0 += t.x + t.y;
            t = __half22float2(*(__half2*)&pf[k2][2]); l0 += t.x + t.y;
            t = __half22float2(*(__half2*)&pf[k2][1]); l1 += t.x + t.y;
            t = __half22float2(*(__half2*)&pf[k2][3]); l1 += t.x + t.y;
        }

        // O += P @ V : warp 16x128, k=64 ; V via ldmatrix.trans
        #pragma unroll
        for (int k2 = 0; k2 < 4; ++k2) {
            #pragma unroll
            for (int nb = 0; nb < 8; nb++) {
                int kr = k2*16 + (lane & 15);
                int ch = nb*2 + (lane >> 4);
                uint32_t q[4];
                ldsm4t(q, sV + (uint32_t)kr*256 +
                          ((uint32_t)((ch & 8) | ((ch ^ (kr & 7)) & 7)) << 4));
                uint32_t bf0[2] = {q[0], q[1]}, bf1[2] = {q[2], q[3]};
                mma16(oacc[2*nb],   pf[k2], bf0);
                mma16(oacc[2*nb+1], pf[k2], bf1);
            }
        }
    }

    l0 += __shfl_xor_sync(0xffffffff, l0, 1);
    l0 += __shfl_xor_sync(0xffffffff, l0, 2);
    l1 += __shfl_xor_sync(0xffffffff, l1, 1);
    l1 += __shfl_xor_sync(0xffffffff, l1, 2);
    const float inv0 = 1.f / l0, inv1 = 1.f / l1;

    const int r0 = q0 + wrow + gid;
    #pragma unroll
    for (int nt = 0; nt < 16; nt++) {
        int col = h*HD + nt*8 + 2*tig;
        *(uint32_t*)(AOh + (size_t)r0 * DMODEL + col) =
            f2h2(oacc[nt][0]*inv0, oacc[nt][1]*inv0);
        *(uint32_t*)(AOh + (size_t)(r0 + 8) * DMODEL + col) =
            f2h2(oacc[nt][2]*inv1, oacc[nt][3]*inv1);
    }
}

// ---------------- launch -----------------------------------------------------
extern "C" void kernel_launch(void* const* d_in, const int* in_sizes, int n_in,
                              void* d_out, int out_size)
{
    const float* x  = (const float*)d_in[0];
    const float* Wq = (const float*)d_in[1];
    const float* Wk = (const float*)d_in[2];
    const float* Wv = (const float*)d_in[3];
    const float* Wo = (const float*)d_in[4];
    float* out = (float*)d_out;

    float *Q, *K, *V;
    __half *xh, *Wqh, *Wkh, *Wvh, *Woh, *Qh, *Kh, *Vh, *AOh;
    cudaGetSymbolAddress((void**)&Q,   g_Q);
    cudaGetSymbolAddress((void**)&K,   g_K);
    cudaGetSymbolAddress((void**)&V,   g_V);
    cudaGetSymbolAddress((void**)&xh,  g_xh);
    cudaGetSymbolAddress((void**)&Wqh, g_Wqh);
    cudaGetSymbolAddress((void**)&Wkh, g_Wkh);
    cudaGetSymbolAddress((void**)&Wvh, g_Wvh);
    cudaGetSymbolAddress((void**)&Woh, g_Woh);
    cudaGetSymbolAddress((void**)&Qh,  g_Qh);
    cudaGetSymbolAddress((void**)&Kh,  g_Kh);
    cudaGetSymbolAddress((void**)&Vh,  g_Vh);
    cudaGetSymbolAddress((void**)&AOh, g_AOh);

    cudaFuncSetAttribute(hgemm,    cudaFuncAttributeMaxDynamicSharedMemorySize, GEMM_SMEM);
    cudaFuncSetAttribute(flash_h2, cudaFuncAttributeMaxDynamicSharedMemorySize, FLASH_SMEM);

    rope_table_kernel<<<(T_SEQ*64 + 255)/256, 256>>>();
    conv_all<<<(int)((CONV_TOTAL + 255)/256), 256>>>(x, Wq, Wk, Wv, Wo);

    // fused QKV projection: tiles 0-15 -> Wq/Q, 16-19 -> Wk/K, 20-23 -> Wv/V
    hgemm<<<dim3(24, M_ROWS/128), 256, GEMM_SMEM>>>(
        xh, Wqh, Wkh, Wvh, Q, K, V, 16, 4, DMODEL);

    rope_half_kernel<<<(M_ROWS*HQ*32  + 255)/256, 256>>>(Q, Qh, HQ, FA_SCALE);
    rope_half_kernel<<<(M_ROWS*HKV*32 + 255)/256, 256>>>(K, Kh, HKV, 1.0f);
    v_half_kernel<<<(M_ROWS*DKV/4 + 255)/256, 256>>>(V, Vh);

    flash_h2<<<dim3(16, HQ, BATCH), 256, FLASH_SMEM>>>(Qh, Kh, Vh, AOh);

    // output projection
    hgemm<<<dim3(16, M_ROWS/128), 256, GEMM_SMEM>>>(
        AOh, Woh, Woh, Woh, out, out, out, 16, 0, DMODEL);
}

// round 7
// speedup vs baseline: 10.7830x; 1.0239x over previous
#include <cuda_runtime.h>
#include <cuda_fp16.h>
#include <math.h>
#include <stdint.h>

#define T_SEQ 2048
#define BATCH 2
#define DMODEL 2048
#define HQ 16
#define HKV 4
#define HD 128
#define M_ROWS (BATCH*T_SEQ)   /* 4096 */
#define DKV (HKV*HD)           /* 512 */
#define FA_SCALE 0.08838834764831845f
#define LOG2E 1.4426950408889634f

// ---------------- scratch ---------------------------------------------------
__device__ __half g_xh[M_ROWS*DMODEL];
__device__ __half g_Wqh[DMODEL*DMODEL];
__device__ __half g_Wkh[DMODEL*DKV];
__device__ __half g_Wvh[DMODEL*DKV];
__device__ __half g_Woh[DMODEL*DMODEL];
__device__ __half g_Qh[M_ROWS*DMODEL];
__device__ __half g_Kh[M_ROWS*DKV];
__device__ __half g_Vh[M_ROWS*DKV];
__device__ __half g_AOh[M_ROWS*DMODEL];
__device__ float  g_cos[T_SEQ*64];
__device__ float  g_sin[T_SEQ*64];

// ---------------- helpers ----------------------------------------------------
__device__ __forceinline__ uint32_t f2h2(float a, float b) {
    __half2 h = __halves2half2(__float2half_rn(a), __float2half_rn(b));
    return *reinterpret_cast<uint32_t*>(&h);
}
__device__ __forceinline__ uint32_t cvta_smem(const void* p) {
    uint32_t a;
    asm("{ .reg .u64 t; cvta.to.shared.u64 t, %1; cvt.u32.u64 %0, t; }"
        : "=r"(a) : "l"(p));
    return a;
}
__device__ __forceinline__ void mma16(float* d, const uint32_t* a, const uint32_t* b) {
    asm volatile("mma.sync.aligned.m16n8k16.row.col.f32.f16.f16.f32 "
        "{%0,%1,%2,%3}, {%4,%5,%6,%7}, {%8,%9}, {%0,%1,%2,%3};"
        : "+f"(d[0]), "+f"(d[1]), "+f"(d[2]), "+f"(d[3])
        : "r"(a[0]), "r"(a[1]), "r"(a[2]), "r"(a[3]), "r"(b[0]), "r"(b[1]));
}
__device__ __forceinline__ void ldsm4(uint32_t* r, uint32_t a) {
    asm volatile("ldmatrix.sync.aligned.m8n8.x4.shared.b16 {%0,%1,%2,%3}, [%4];"
        : "=r"(r[0]), "=r"(r[1]), "=r"(r[2]), "=r"(r[3]) : "r"(a));
}
__device__ __forceinline__ void ldsm4t(uint32_t* r, uint32_t a) {
    asm volatile("ldmatrix.sync.aligned.m8n8.x4.trans.shared.b16 {%0,%1,%2,%3}, [%4];"
        : "=r"(r[0]), "=r"(r[1]), "=r"(r[2]), "=r"(r[3]) : "r"(a));
}
__device__ __forceinline__ void cp16(uint32_t dst, const void* src) {
    asm volatile("cp.async.cg.shared.global [%0], [%1], 16;" :: "r"(dst), "l"(src));
}
#define CPCOMMIT() asm volatile("cp.async.commit_group;" ::: "memory")
#define CPWAIT1()  asm volatile("cp.async.wait_group 1;" ::: "memory")
#define CPWAIT0()  asm volatile("cp.async.wait_group 0;" ::: "memory")

// ---------------- input conversion fp32 -> fp16 ------------------------------
#define N_X  ((long)M_ROWS*DMODEL/4)
#define N_WQ ((long)DMODEL*DMODEL/4)
#define N_WK ((long)DMODEL*DKV/4)
#define CONV_TOTAL (N_X + 2*N_WQ + 2*N_WK)

__global__ void conv_all(const float* __restrict__ x, const float* __restrict__ wq,
                         const float* __restrict__ wk, const float* __restrict__ wv,
                         const float* __restrict__ wo) {
    long i = (long)blockIdx.x*256 + threadIdx.x;
    const float* src; __half* dst; long off;
    if (i < N_X)                       { src = x;  dst = g_xh;  off = i; }
    else if (i < N_X + N_WQ)           { src = wq; dst = g_Wqh; off = i - N_X; }
    else if (i < N_X + N_WQ + N_WK)    { src = wk; dst = g_Wkh; off = i - N_X - N_WQ; }
    else if (i < N_X + N_WQ + 2*N_WK)  { src = wv; dst = g_Wvh; off = i - N_X - N_WQ - N_WK; }
    else if (i < CONV_TOTAL)           { src = wo; dst = g_Woh; off = i - N_X - N_WQ - 2*N_WK; }
    else return;
    float4 v = *(const float4*)(src + off*4);
    uint2 u; u.x = f2h2(v.x, v.y); u.y = f2h2(v.z, v.w);
    *(uint2*)(dst + off*4) = u;
}

// ---------------- RoPE ------------------------------------------------------
__global__ void rope_table_kernel() {
    int idx = blockIdx.x*blockDim.x + threadIdx.x;
    if (idx >= T_SEQ*64) return;
    int t = idx >> 6, i = idx & 63;
    float inv = powf(10000.0f, -(float)i / 64.0f);
    float ang = (float)t * inv;
    g_cos[idx] = (float)cos((double)ang);
    g_sin[idx] = (float)sin((double)ang);
}

// in-place fp16 RoPE (each thread reads+writes only its own two words)
__global__ void rope_h16_kernel(__half* __restrict__ buf, int heads, float scale) {
    int idx = blockIdx.x*blockDim.x + threadIdx.x;
    int total = M_ROWS * heads * 32;
    if (idx >= total) return;
    int i2 = idx & 31;
    int h = (idx >> 5) % heads;
    int m = idx / (32 * heads);
    int t = m & (T_SEQ - 1);
    int d0 = 2*i2;
    uint32_t* p = (uint32_t*)(buf + (size_t)m * heads * HD + h * HD);
    float2 a = __half22float2(*(__half2*)&p[i2]);
    float2 b = __half22float2(*(__half2*)&p[32 + i2]);
    float c0 = g_cos[t*64 + d0], c1 = g_cos[t*64 + d0 + 1];
    float s0 = g_sin[t*64 + d0], s1 = g_sin[t*64 + d0 + 1];
    p[i2]      = f2h2((a.x*c0 - b.x*s0)*scale, (a.y*c1 - b.y*s1)*scale);
    p[32 + i2] = f2h2((b.x*c0 + a.x*s0)*scale, (b.y*c1 + a.y*s1)*scale);
}

// ---------------- fp16 GEMM: cp.async 3-stage + ldmatrix ---------------------
// C[M,N] = A[M,K](fp16) @ B[K,N](fp16). 128x128 CTA, 8 warps (4x2), BK=64.
// half_out: C is __half*, else float*.
#define GSTB 32768
#define GEMM_SMEM (3*GSTB)

__global__ __launch_bounds__(256) void hgemm(
    const __half* __restrict__ A,
    const __half* __restrict__ B0, const __half* __restrict__ B1, const __half* __restrict__ B2,
    void* __restrict__ C0, void* __restrict__ C1, void* __restrict__ C2,
    int t0, int t1, int K, int half_out)
{
    extern __shared__ char gsm[];
    const uint32_t sb = cvta_smem(gsm);

    const int tx = blockIdx.x;
    const __half* B; void* C; int N, cb;
    if (tx < t0)           { B = B0; C = C0; N = t0*128; cb = tx*128; }
    else if (tx < t0 + t1) { B = B1; C = C1; N = t1*128; cb = (tx - t0)*128; }
    else { B = B2; C = C2; N = ((int)gridDim.x - t0 - t1)*128; cb = (tx - t0 - t1)*128; }

    const int tid = threadIdx.x;
    const int lane = tid & 31, wid = tid >> 5;
    const int gid = lane >> 2, tig = lane & 3;
    const int wm = wid & 3, wn = wid >> 2;
    const int bm = blockIdx.y * 128;
    const int nc = K >> 6;

    const int ar = tid >> 3, ac = tid & 7;
    const int bk = tid >> 4, bc = tid & 15;
    const uint32_t aswz = (uint32_t)(ac ^ (ar & 7)) << 4;
    const uint32_t bswz = (uint32_t)((bc & 8) | ((bc ^ (bk & 7)) & 7)) << 4;

    auto issue = [&](int c) {
        const uint32_t sA = sb + (c % 3)*GSTB;
        const uint32_t sB = sA + 16384;
        const __half* Ag = A + (size_t)(bm + ar)*K + c*64 + ac*8;
        #pragma unroll
        for (int i = 0; i < 4; i++)
            cp16(sA + (uint32_t)(ar + 32*i)*128 + aswz, Ag + (size_t)(32*i)*K);
        const __half* Bg = B + (size_t)(c*64 + bk)*N + cb + bc*8;
        #pragma unroll
        for (int i = 0; i < 4; i++)
            cp16(sB + (uint32_t)(bk + 16*i)*256 + bswz, Bg + (size_t)(16*i)*N);
        CPCOMMIT();
    };

    float acc[2][8][4];
    #pragma unroll
    for (int mt = 0; mt < 2; mt++)
        #pragma unroll
        for (int nt = 0; nt < 8; nt++)
            #pragma unroll
            for (int e = 0; e < 4; e++) acc[mt][nt][e] = 0.f;

    issue(0); issue(1);

    for (int c = 0; c < nc; ++c) {
        if (c + 2 < nc) { CPWAIT1(); } else { CPWAIT0(); }
        __syncthreads();
        if (c + 2 < nc) issue(c + 2);

        const uint32_t sA = sb + (c % 3)*GSTB;
        const uint32_t sB = sA + 16384;

        #pragma unroll
        for (int ks = 0; ks < 4; ++ks) {
            uint32_t af[2][4];
            #pragma unroll
            for (int mt = 0; mt < 2; mt++) {
                int row = wm*32 + mt*16 + (lane & 15);
                int ch = ks*2 + (lane >> 4);
                ldsm4(af[mt], sA + (uint32_t)row*128 + ((uint32_t)(ch ^ (row & 7)) << 4));
            }
            uint32_t bf[8][2];
            #pragma unroll
            for (int nb = 0; nb < 4; nb++) {
                int kr = ks*16 + (lane & 15);
                int ch = wn*8 + nb*2 + (lane >> 4);
                uint32_t q[4];
                ldsm4t(q, sB + (uint32_t)kr*256 +
                          ((uint32_t)((ch & 8) | ((ch ^ (kr & 7)) & 7)) << 4));
                bf[2*nb][0] = q[0]; bf[2*nb][1] = q[1];
                bf[2*nb+1][0] = q[2]; bf[2*nb+1][1] = q[3];
            }
            #pragma unroll
            for (int mt = 0; mt < 2; mt++)
                #pragma unroll
                for (int nt = 0; nt < 8; nt++)
                    mma16(acc[mt][nt], af[mt], bf[nt]);
        }
    }

    if (half_out) {
        __half* Ch = (__half*)C;
        #pragma unroll
        for (int mt = 0; mt < 2; mt++) {
            int r0 = bm + wm*32 + mt*16 + gid;
            #pragma unroll
            for (int nt = 0; nt < 8; nt++) {
                int col = cb + wn*64 + nt*8 + 2*tig;
                *(uint32_t*)(Ch + (size_t)r0 * N + col)       = f2h2(acc[mt][nt][0], acc[mt][nt][1]);
                *(uint32_t*)(Ch + (size_t)(r0 + 8) * N + col) = f2h2(acc[mt][nt][2], acc[mt][nt][3]);
            }
        }
    } else {
        float* Cf = (float*)C;
        #pragma unroll
        for (int mt = 0; mt < 2; mt++) {
            int r0 = bm + wm*32 + mt*16 + gid;
            #pragma unroll
            for (int nt = 0; nt < 8; nt++) {
                int col = cb + wn*64 + nt*8 + 2*tig;
                *(float2*)(Cf + (size_t)r0 * N + col)       = make_float2(acc[mt][nt][0], acc[mt][nt][1]);
                *(float2*)(Cf + (size_t)(r0 + 8) * N + col) = make_float2(acc[mt][nt][2], acc[mt][nt][3]);
            }
        }
    }
}

// ---------------- flash attention: Q frags in regs, 3-stage KV ---------------
// 256 threads (8 warps), BQ=128 (warp = 16 rows), BK=64.
// SMEM: Q 32KB @0 ; 3 stages of (K 16KB + V 16KB).
#define FKVSTB 32768
#define FLASH_SMEM (32768 + 3*FKVSTB)

__global__ __launch_bounds__(256) void flash_h2(
    const __half* __restrict__ Qh, const __half* __restrict__ Kh,
    const __half* __restrict__ Vh, __half* __restrict__ AOh)
{
    extern __shared__ char fsm[];
    const uint32_t sb = cvta_smem(fsm);
    const int tid = threadIdx.x, lane = tid & 31, wid = tid >> 5;
    const int gid = lane >> 2, tig = lane & 3;
    const int qt = 15 - blockIdx.x;
    const int h = blockIdx.y, b = blockIdx.z;
    const int hk = h >> 2;
    const int wrow = wid * 16;
    const int q0 = b*T_SEQ + qt*128;
    const int nkt = 2*qt + 2;

    auto issue_kv = [&](int kt) {
        const uint32_t sK = sb + 32768 + (kt % 3)*FKVSTB;
        const uint32_t sV = sK + 16384;
        const int k0g = b*T_SEQ + kt*64;
        const __half* Kg = Kh + (size_t)k0g*DKV + hk*HD;
        const __half* Vg = Vh + (size_t)k0g*DKV + hk*HD;
        #pragma unroll
        for (int i = 0; i < 4; i++) {
            int id = tid + 256*i;
            int r = id >> 4, c = id & 15;
            uint32_t o = (uint32_t)r*256 + ((uint32_t)((c & 8) | ((c ^ (r & 7)) & 7)) << 4);
            cp16(sK + o, Kg + (size_t)r*DKV + c*8);
            cp16(sV + o, Vg + (size_t)r*DKV + c*8);
        }
        CPCOMMIT();
    };

    // group 0: Q tile + KV(0); group 1: KV(1)
    {
        const __half* Qg = Qh + (size_t)q0*DMODEL + h*HD;
        #pragma unroll
        for (int i = 0; i < 8; i++) {
            int id = tid + 256*i;
            int r = id >> 4, c = id & 15;
            uint32_t o = (uint32_t)r*256 + ((uint32_t)((c & 8) | ((c ^ (r & 7)) & 7)) << 4);
            cp16(sb + o, Qg + (size_t)r*DMODEL + c*8);
        }
        const __half* Kg = Kh + (size_t)(b*T_SEQ)*DKV + hk*HD;
        const __half* Vg = Vh + (size_t)(b*T_SEQ)*DKV + hk*HD;
        const uint32_t sK = sb + 32768, sV = sK + 16384;
        #pragma unroll
        for (int i = 0; i < 4; i++) {
            int id = tid + 256*i;
            int r = id >> 4, c = id & 15;
            uint32_t o = (uint32_t)r*256 + ((uint32_t)((c & 8) | ((c ^ (r & 7)) & 7)) << 4);
            cp16(sK + o, Kg + (size_t)r*DKV + c*8);
            cp16(sV + o, Vg + (size_t)r*DKV + c*8);
        }
        CPCOMMIT();
        issue_kv(1);
    }

    float oacc[16][4];
    #pragma unroll
    for (int nt = 0; nt < 16; nt++)
        #pragma unroll
        for (int e = 0; e < 4; e++) oacc[nt][e] = 0.f;
    float l0 = 0.f, l1 = 0.f;

    uint32_t qf[8][4];      // Q fragments, ktile-invariant
    bool qloaded = false;

    for (int kt = 0; kt < nkt; ++kt) {
        if (kt + 2 < nkt) { CPWAIT1(); } else { CPWAIT0(); }
        __syncthreads();
        if (kt + 2 < nkt) issue_kv(kt + 2);

        if (!qloaded) {     // after first wait: Q resident; load frags once
            #pragma unroll
            for (int ks = 0; ks < 8; ++ks) {
                int row = wrow + (lane & 15);
                int ch = ks*2 + (lane >> 4);
                ldsm4(qf[ks], sb + (uint32_t)row*256 +
                          ((uint32_t)((ch & 8) | ((ch ^ (row & 7)) & 7)) << 4));
            }
            qloaded = true;
        }

        const uint32_t sK = sb + 32768 + (kt % 3)*FKVSTB;
        const uint32_t sV = sK + 16384;

        // S = Q @ K^T : warp 16x64, k=128
        float sacc[8][4];
        #pragma unroll
        for (int nt = 0; nt < 8; nt++)
            #pragma unroll
            for (int e = 0; e < 4; e++) sacc[nt][e] = 0.f;

        #pragma unroll
        for (int ks = 0; ks < 8; ++ks) {
            #pragma unroll
            for (int np = 0; np < 4; np++) {
                int row = np*16 + (lane & 15);
                int ch = ks*2 + (lane >> 4);
                uint32_t q[4];
                ldsm4(q, sK + (uint32_t)row*256 +
                          ((uint32_t)((ch & 8) | ((ch ^ (row & 7)) & 7)) << 4));
                uint32_t bf0[2] = {q[0], q[2]}, bf1[2] = {q[1], q[3]};
                mma16(sacc[2*np],   qf[ks], bf0);
                mma16(sacc[2*np+1], qf[ks], bf1);
            }
        }

        // mask + exp2 + pack P into A-fragments (Q pre-scaled by scale*log2e)
        const int qg0 = qt*128 + wrow + gid;
        const int kb  = kt*64;
        uint32_t pf[4][4];
        #pragma unroll
        for (int k2 = 0; k2 < 4; ++k2) {
            float p[2][4];
            #pragma unroll
            for (int j = 0; j < 2; j++) {
                int nt = 2*k2 + j;
                int c0 = kb + nt*8 + 2*tig;
                p[j][0] = (c0     <= qg0    ) ? exp2f(sacc[nt][0]) : 0.f;
                p[j][1] = (c0 + 1 <= qg0    ) ? exp2f(sacc[nt][1]) : 0.f;
                p[j][2] = (c0     <= qg0 + 8) ? exp2f(sacc[nt][2]) : 0.f;
                p[j][3] = (c0 + 1 <= qg0 + 8) ? exp2f(sacc[nt][3]) : 0.f;
            }
            pf[k2][0] = f2h2(p[0][0], p[0][1]);
            pf[k2][1] = f2h2(p[0][2], p[0][3]);
            pf[k2][2] = f2h2(p[1][0], p[1][1]);
            pf[k2][3] = f2h2(p[1][2], p[1][3]);
            float2 t;
            t = __half22float2(*(__half2*)&pf[k2][0]); l0 += t.x + t.y;
            t = __half22float2(*(__half2*)&pf[k2][2]); l0 += t.x + t.y;
            t = __half22float2(*(__half2*)&pf[k2][1]); l1 += t.x + t.y;
            t = __half22float2(*(__half2*)&pf[k2][3]); l1 += t.x + t.y;
        }

        // O += P @ V : warp 16x128, k=64 ; V via ldmatrix.trans
        #pragma unroll
        for (int k2 = 0; k2 < 4; ++k2) {
            #pragma unroll
            for (int nb = 0; nb < 8; nb++) {
                int kr = k2*16 + (lane & 15);
                int ch = nb*2 + (lane >> 4);
                uint32_t q[4];
                ldsm4t(q, sV + (uint32_t)kr*256 +
                          ((uint32_t)((ch & 8) | ((ch ^ (kr & 7)) & 7)) << 4));
                uint32_t bf0[2] = {q[0], q[1]}, bf1[2] = {q[2], q[3]};
                mma16(oacc[2*nb],   pf[k2], bf0);
                mma16(oacc[2*nb+1], pf[k2], bf1);
            }
        }
    }

    l0 += __shfl_xor_sync(0xffffffff, l0, 1);
    l0 += __shfl_xor_sync(0xffffffff, l0, 2);
    l1 += __shfl_xor_sync(0xffffffff, l1, 1);
    l1 += __shfl_xor_sync(0xffffffff, l1, 2);
    const float inv0 = 1.f / l0, inv1 = 1.f / l1;

    const int r0 = q0 + wrow + gid;
    #pragma unroll
    for (int nt = 0; nt < 16; nt++) {
        int col = h*HD + nt*8 + 2*tig;
        *(uint32_t*)(AOh + (size_t)r0 * DMODEL + col) =
            f2h2(oacc[nt][0]*inv0, oacc[nt][1]*inv0);
        *(uint32_t*)(AOh + (size_t)(r0 + 8) * DMODEL + col) =
            f2h2(oacc[nt][2]*inv1, oacc[nt][3]*inv1);
    }
}

// ---------------- launch -----------------------------------------------------
extern "C" void kernel_launch(void* const* d_in, const int* in_sizes, int n_in,
                              void* d_out, int out_size)
{
    const float* x  = (const float*)d_in[0];
    const float* Wq = (const float*)d_in[1];
    const float* Wk = (const float*)d_in[2];
    const float* Wv = (const float*)d_in[3];
    const float* Wo = (const float*)d_in[4];
    float* out = (float*)d_out;

    __half *xh, *Wqh, *Wkh, *Wvh, *Woh, *Qh, *Kh, *Vh, *AOh;
    cudaGetSymbolAddress((void**)&xh,  g_xh);
    cudaGetSymbolAddress((void**)&Wqh, g_Wqh);
    cudaGetSymbolAddress((void**)&Wkh, g_Wkh);
    cudaGetSymbolAddress((void**)&Wvh, g_Wvh);
    cudaGetSymbolAddress((void**)&Woh, g_Woh);
    cudaGetSymbolAddress((void**)&Qh,  g_Qh);
    cudaGetSymbolAddress((void**)&Kh,  g_Kh);
    cudaGetSymbolAddress((void**)&Vh,  g_Vh);
    cudaGetSymbolAddress((void**)&AOh, g_AOh);

    cudaFuncSetAttribute(hgemm,    cudaFuncAttributeMaxDynamicSharedMemorySize, GEMM_SMEM);
    cudaFuncSetAttribute(flash_h2, cudaFuncAttributeMaxDynamicSharedMemorySize, FLASH_SMEM);

    rope_table_kernel<<<(T_SEQ*64 + 255)/256, 256>>>();
    conv_all<<<(int)((CONV_TOTAL + 255)/256), 256>>>(x, Wq, Wk, Wv, Wo);

    // fused QKV projection (fp16 out): tiles 0-15 -> Q, 16-19 -> K, 20-23 -> V
    hgemm<<<dim3(24, M_ROWS/128), 256, GEMM_SMEM>>>(
        xh, Wqh, Wkh, Wvh, Qh, Kh, Vh, 16, 4, DMODEL, 1);

    // in-place RoPE; Q pre-scaled by FA_SCALE*log2(e) so flash uses exp2
    rope_h16_kernel<<<(M_ROWS*HQ*32  + 255)/256, 256>>>(Qh, HQ, FA_SCALE*LOG2E);
    rope_h16_kernel<<<(M_ROWS*HKV*32 + 255)/256, 256>>>(Kh, HKV, 1.0f);

    flash_h2<<<dim3(16, HQ, BATCH), 256, FLASH_SMEM>>>(Qh, Kh, Vh, AOh);

    // output projection (fp32 out)
    hgemm<<<dim3(16, M_ROWS/128), 256, GEMM_SMEM>>>(
        AOh, Woh, Woh, Woh, out, out, out, 16, 0, DMODEL, 0);
}